// round 15
// baseline (speedup 1.0000x reference)
#include <cuda_runtime.h>
#include <cuda_fp16.h>
#include <cuda_bf16.h>
#include <math.h>

#define Nn 100000
#define Ee 1600000
#define Gg 64

// ---------------- packed f32x2 helpers ----------------
#define PACK2(out, a, b) \
    asm("mov.b64 %0, {%1, %2};" : "=l"(out) : "f"(a), "f"(b))
#define FMA2(acc, a, b) \
    asm("fma.rn.f32x2 %0, %1, %2, %0;" : "+l"(acc) : "l"(a), "l"(b))

// ---------------- device scratch (static, no runtime allocation) ----------------
__device__ int    g_cnt[Nn];
__device__ int    g_rowptr[Nn + 1];
__device__ int    g_cursor[Nn];
__device__ int    g_cols[Ee];
__device__ float  g_dis[Nn];
__device__ __half g_hA[Nn * 64];        // gemm1 out (dis-prescaled), fp16
__device__ __half g_hB[Nn * 64];        // gather64 out (pre-BN1), fp16
__device__ float  g_fA[Nn * 32];        // gemm2 out / gemm3 out (fp32)
__device__ float  g_fB[Nn * 32];        // gather32 out / gather16 out (fp32)
__device__ float  g_stats[3 * 128];     // per layer: [0..H) sum, [H..2H) sumsq
__device__ int    g_bsum[256];          // scan partials
__device__ float  g_pool[Gg * 33];      // per graph: sum[16], max[16], count

// ---------------- small utility kernels (exact round-5) -------------------------
__global__ void k_zero() {
    int i = blockIdx.x * 256 + threadIdx.x;
    if (i < Nn) g_cnt[i] = 0;
    if (i < 3 * 128) g_stats[i] = 0.f;
}
__global__ void k_hist(const int* __restrict__ dst) {
    int e = blockIdx.x * 256 + threadIdx.x;
    if (e < Ee) atomicAdd(&g_cnt[dst[e]], 1);
}
__global__ void k_dis() {
    int i = blockIdx.x * 256 + threadIdx.x;
    if (i < Nn) g_dis[i] = rsqrtf((float)(g_cnt[i] + 1));
}

#define SCAN_NB 196   // 196 * 512 = 100352 >= Nn

__global__ void k_scan1() {
    __shared__ int sh[512];
    int t = threadIdx.x, idx = blockIdx.x * 512 + t;
    sh[t] = (idx < Nn) ? g_cnt[idx] : 0;
    __syncthreads();
    for (int off = 256; off > 0; off >>= 1) {
        if (t < off) sh[t] += sh[t + off];
        __syncthreads();
    }
    if (t == 0) g_bsum[blockIdx.x] = sh[0];
}
__global__ void k_scan2() {
    __shared__ int sh[256];
    int t = threadIdx.x;
    int v = (t < SCAN_NB) ? g_bsum[t] : 0;
    sh[t] = v;
    __syncthreads();
    for (int off = 1; off < 256; off <<= 1) {
        int add = (t >= off) ? sh[t - off] : 0;
        __syncthreads();
        sh[t] += add;
        __syncthreads();
    }
    if (t < SCAN_NB) g_bsum[t] = sh[t] - v;   // exclusive
    if (t == 0) g_rowptr[Nn] = Ee;
}
__global__ void k_scan3() {
    __shared__ int sh[512];
    int t = threadIdx.x, idx = blockIdx.x * 512 + t;
    int v = (idx < Nn) ? g_cnt[idx] : 0;
    sh[t] = v;
    __syncthreads();
    for (int off = 1; off < 512; off <<= 1) {
        int add = (t >= off) ? sh[t - off] : 0;
        __syncthreads();
        sh[t] += add;
        __syncthreads();
    }
    if (idx < Nn) {
        int ex = g_bsum[blockIdx.x] + sh[t] - v;
        g_rowptr[idx] = ex;
        g_cursor[idx] = ex;
    }
}
__global__ void k_fill(const int* __restrict__ src, const int* __restrict__ dst) {
    int e = blockIdx.x * 256 + threadIdx.x;
    if (e < Ee) {
        int d = dst[e];
        int p = atomicAdd(&g_cursor[d], 1);
        g_cols[p] = src[e];
    }
}

// ---------------- GEMM (round-5 body; templated input/output types) -------------
// out[i,c] = dis[i] * sum_k f(h[i,k]) * W[k,c]
// TI: float or __half input; TO: float or __half output; fp32 math throughout.
template <typename TI, typename TO, int K, int H, bool NORM>
__global__ void __launch_bounds__(128, 4) k_gemm(const TI* __restrict__ h,
                                                 const float* __restrict__ W,
                                                 const float* __restrict__ stats,
                                                 const float* __restrict__ gamma,
                                                 const float* __restrict__ beta,
                                                 TO* __restrict__ out) {
    constexpr int C = H / 4;
    __shared__ float Wsm[16 * H];
    __shared__ float xt[16][128];
    __shared__ float nsc[K], nsh[K];
    const int tid = threadIdx.x;
    const int base = blockIdx.x * 128;
    const int n0 = (tid & 31) * 4;
    const int cg = tid >> 5;
    const int cbase = cg * C;

    if (NORM) {
        for (int c = tid; c < K; c += 128) {
            float m = stats[c] * (1.0f / Nn);
            float var = stats[K + c] * (1.0f / Nn) - m * m;
            float rstd = rsqrtf(var + 1e-5f);
            float sc = rstd * gamma[c];
            nsc[c] = sc;
            nsh[c] = beta[c] - m * sc;
        }
        __syncthreads();
    }

    unsigned long long acc2[4][C / 2];
#pragma unroll
    for (int t = 0; t < 4; t++)
#pragma unroll
        for (int j = 0; j < C / 2; j++) acc2[t][j] = 0ull;

    const int myrow = base + tid;

    for (int kc = 0; kc < K; kc += 16) {
        {
            const float4* Wg = reinterpret_cast<const float4*>(W + kc * H);
            float4* Ws = reinterpret_cast<float4*>(Wsm);
#pragma unroll
            for (int i = tid; i < 16 * H / 4; i += 128) Ws[i] = Wg[i];
        }
        // stage x chunk transposed: xt[kk][tid] = f(h[base+tid][kc+kk])
        if constexpr (sizeof(TI) == 4) {
#pragma unroll
            for (int q = 0; q < 4; q++) {
                float4 v = make_float4(0.f, 0.f, 0.f, 0.f);
                if (myrow < Nn)
                    v = *reinterpret_cast<const float4*>(
                        reinterpret_cast<const float*>(h) + (size_t)myrow * K + kc + q * 4);
                if (NORM) {
                    int cb = kc + q * 4;
                    v.x = v.x * nsc[cb + 0] + nsh[cb + 0]; v.x = v.x > 0.f ? v.x : 0.1f * v.x;
                    v.y = v.y * nsc[cb + 1] + nsh[cb + 1]; v.y = v.y > 0.f ? v.y : 0.1f * v.y;
                    v.z = v.z * nsc[cb + 2] + nsh[cb + 2]; v.z = v.z > 0.f ? v.z : 0.1f * v.z;
                    v.w = v.w * nsc[cb + 3] + nsh[cb + 3]; v.w = v.w > 0.f ? v.w : 0.1f * v.w;
                }
                xt[q * 4 + 0][tid] = v.x;
                xt[q * 4 + 1][tid] = v.y;
                xt[q * 4 + 2][tid] = v.z;
                xt[q * 4 + 3][tid] = v.w;
            }
        } else {
            // half input: 16 halves = 32B = 2 x uint4
            uint4 u[2];
            u[0] = make_uint4(0, 0, 0, 0);
            u[1] = make_uint4(0, 0, 0, 0);
            if (myrow < Nn) {
                const uint4* hp = reinterpret_cast<const uint4*>(
                    reinterpret_cast<const __half*>(h) + (size_t)myrow * K + kc);
                u[0] = hp[0];
                u[1] = hp[1];
            }
#pragma unroll
            for (int q = 0; q < 2; q++) {
                unsigned words[4] = {u[q].x, u[q].y, u[q].z, u[q].w};
#pragma unroll
                for (int wI = 0; wI < 4; wI++) {
                    __half2 hh = *reinterpret_cast<__half2*>(&words[wI]);
                    float2 f = __half22float2(hh);
                    int cb = kc + q * 8 + wI * 2;
                    if (NORM) {
                        f.x = f.x * nsc[cb + 0] + nsh[cb + 0];
                        f.x = f.x > 0.f ? f.x : 0.1f * f.x;
                        f.y = f.y * nsc[cb + 1] + nsh[cb + 1];
                        f.y = f.y > 0.f ? f.y : 0.1f * f.y;
                    }
                    xt[q * 8 + wI * 2 + 0][tid] = f.x;
                    xt[q * 8 + wI * 2 + 1][tid] = f.y;
                }
            }
        }
        __syncthreads();
#pragma unroll
        for (int kk = 0; kk < 16; kk++) {
            float4 xv = *reinterpret_cast<const float4*>(&xt[kk][n0]);
            unsigned long long x0, x1, x2, x3;
            PACK2(x0, xv.x, xv.x);
            PACK2(x1, xv.y, xv.y);
            PACK2(x2, xv.z, xv.z);
            PACK2(x3, xv.w, xv.w);
            const ulonglong2* w2 =
                reinterpret_cast<const ulonglong2*>(&Wsm[kk * H + cbase]);
#pragma unroll
            for (int j = 0; j < C / 4; j++) {
                ulonglong2 w = w2[j];
                FMA2(acc2[0][2 * j + 0], x0, w.x);
                FMA2(acc2[0][2 * j + 1], x0, w.y);
                FMA2(acc2[1][2 * j + 0], x1, w.x);
                FMA2(acc2[1][2 * j + 1], x1, w.y);
                FMA2(acc2[2][2 * j + 0], x2, w.x);
                FMA2(acc2[2][2 * j + 1], x2, w.y);
                FMA2(acc2[3][2 * j + 0], x3, w.x);
                FMA2(acc2[3][2 * j + 1], x3, w.y);
            }
        }
        __syncthreads();
    }

    // epilogue: scale by dis[node], store C channels x 4 nodes
#pragma unroll
    for (int t = 0; t < 4; t++) {
        int node = base + n0 + t;
        if (node < Nn) {
            float dn = g_dis[node];
            const float* a = reinterpret_cast<const float*>(acc2[t]);
            if constexpr (sizeof(TO) == 2) {
                __half2* o = reinterpret_cast<__half2*>(
                    reinterpret_cast<__half*>(out) + (size_t)node * H + cbase);
#pragma unroll
                for (int j = 0; j < C / 2; j++)
                    o[j] = __floats2half2_rn(a[2 * j] * dn, a[2 * j + 1] * dn);
            } else {
                float* o = reinterpret_cast<float*>(out) + (size_t)node * H + cbase;
#pragma unroll
                for (int j = 0; j < C / 4; j++) {
                    float4 r;
                    r.x = a[4 * j + 0] * dn;
                    r.y = a[4 * j + 1] * dn;
                    r.z = a[4 * j + 2] * dn;
                    r.w = a[4 * j + 3] * dn;
                    *reinterpret_cast<float4*>(o + 4 * j) = r;
                }
            }
        }
    }
}

// ---------------- gather H=64, half2: R5 structure, ONE load per edge per lane ---
// Lane owns channel pair {2*lane, 2*lane+1} as a single half2 (4B). Full warp per
// edge (one 128B wavefront per hws row), 4-edge body with dual chains: exactly the
// round-5 loop shape with 8 LDG per iter instead of 12.
__global__ void __launch_bounds__(256) k_gather64h(const __half2* __restrict__ hws,
                                                   const float* __restrict__ b,
                                                   __half2* __restrict__ pre,
                                                   float* __restrict__ stats) {
    const int lane = threadIdx.x & 31;
    const int warp = (blockIdx.x * blockDim.x + threadIdx.x) >> 5;
    const int nwarps = (gridDim.x * blockDim.x) >> 5;
    const int cx = 2 * lane, cy = 2 * lane + 1;

    const float2 bia = make_float2(b[cx], b[cy]);
    float sx = 0.f, sy = 0.f, qx = 0.f, qy = 0.f;

    for (int node = warp; node < Nn; node += nwarps) {
        int r0 = g_rowptr[node], r1 = g_rowptr[node + 1];
        float2 self = __half22float2(hws[(size_t)node * 32 + lane]);
        float ax0 = self.x, ay0 = self.y, ax1 = 0.f, ay1 = 0.f;
        int p = r0;
        for (; p + 4 <= r1; p += 4) {
            int sA = g_cols[p], sB = g_cols[p + 1], sC = g_cols[p + 2], sD = g_cols[p + 3];
            float2 vA = __half22float2(hws[(size_t)sA * 32 + lane]);
            float2 vB = __half22float2(hws[(size_t)sB * 32 + lane]);
            float2 vC = __half22float2(hws[(size_t)sC * 32 + lane]);
            float2 vD = __half22float2(hws[(size_t)sD * 32 + lane]);
            ax0 += vA.x + vC.x; ay0 += vA.y + vC.y;
            ax1 += vB.x + vD.x; ay1 += vB.y + vD.y;
        }
        for (; p < r1; p++) {
            int s = g_cols[p];
            float2 v = __half22float2(hws[(size_t)s * 32 + lane]);
            ax0 += v.x; ay0 += v.y;
        }
        float dn = g_dis[node];
        float vx = dn * (ax0 + ax1) + bia.x;
        float vy = dn * (ay0 + ay1) + bia.y;
        __half2 hv = __floats2half2_rn(vx, vy);
        pre[(size_t)node * 32 + lane] = hv;
        float2 vr = __half22float2(hv);        // stats of the rounded value
        sx += vr.x; sy += vr.y;
        qx += vr.x * vr.x; qy += vr.y * vr.y;
    }
    atomicAdd(&stats[cx], sx);
    atomicAdd(&stats[cy], sy);
    atomicAdd(&stats[64 + cx], qx);
    atomicAdd(&stats[64 + cy], qy);
}

// ---------------- gather (EXACT round-5 body) for H=32/16, fp32 ------------------
template <int H>
__global__ void __launch_bounds__(256) k_gather(const float* __restrict__ hws,
                                                const float* __restrict__ b,
                                                float* __restrict__ pre,
                                                float* __restrict__ stats) {
    constexpr int NCH = (H >= 32) ? H / 32 : 1;
    const int lane = threadIdx.x & 31;
    const int warp = (blockIdx.x * blockDim.x + threadIdx.x) >> 5;
    const int nwarps = (gridDim.x * blockDim.x) >> 5;
    const bool act = (H >= 32) || (lane < H);

    int c[NCH];
#pragma unroll
    for (int j = 0; j < NCH; j++) c[j] = lane + 32 * j;

    float s_sum[NCH], s_sq[NCH];
#pragma unroll
    for (int j = 0; j < NCH; j++) { s_sum[j] = 0.f; s_sq[j] = 0.f; }

    for (int node = warp; node < Nn; node += nwarps) {
        int r0 = g_rowptr[node], r1 = g_rowptr[node + 1];
        float acc[NCH];
        if (act) {
#pragma unroll
            for (int j = 0; j < NCH; j++) acc[j] = hws[(size_t)node * H + c[j]];
        } else {
#pragma unroll
            for (int j = 0; j < NCH; j++) acc[j] = 0.f;
        }
        int p = r0;
        for (; p + 4 <= r1; p += 4) {
            int s0 = g_cols[p], s1 = g_cols[p + 1], s2 = g_cols[p + 2], s3 = g_cols[p + 3];
            if (act) {
#pragma unroll
                for (int j = 0; j < NCH; j++) {
                    float v0 = hws[(size_t)s0 * H + c[j]];
                    float v1 = hws[(size_t)s1 * H + c[j]];
                    float v2 = hws[(size_t)s2 * H + c[j]];
                    float v3 = hws[(size_t)s3 * H + c[j]];
                    acc[j] += (v0 + v1) + (v2 + v3);
                }
            }
        }
        for (; p < r1; p++) {
            int s = g_cols[p];
            if (act) {
#pragma unroll
                for (int j = 0; j < NCH; j++) acc[j] += hws[(size_t)s * H + c[j]];
            }
        }
        if (act) {
            float dn = g_dis[node];
#pragma unroll
            for (int j = 0; j < NCH; j++) {
                float v = dn * acc[j] + b[c[j]];
                pre[(size_t)node * H + c[j]] = v;
                s_sum[j] += v;
                s_sq[j] += v * v;
            }
        }
    }
    if (act) {
#pragma unroll
        for (int j = 0; j < NCH; j++) {
            atomicAdd(&stats[c[j]], s_sum[j]);
            atomicAdd(&stats[H + c[j]], s_sq[j]);
        }
    }
}

// ---------------- pooling (exact round-5) ----------------------------------------
__device__ __forceinline__ int lower_bound_batch(const int* __restrict__ batch, int g) {
    int lo = 0, hi = Nn;
    while (lo < hi) {
        int m = (lo + hi) >> 1;
        if (batch[m] < g) lo = m + 1; else hi = m;
    }
    return lo;
}

__global__ void k_pool(const float* __restrict__ x3, const int* __restrict__ batch,
                       const float* __restrict__ stats,
                       const float* __restrict__ gamma, const float* __restrict__ beta) {
    __shared__ int ss, se;
    __shared__ float ssum[256], smax[256];
    int g = blockIdx.x, t = threadIdx.x;
    if (t == 0) { ss = lower_bound_batch(batch, g); se = lower_bound_batch(batch, g + 1); }
    __syncthreads();
    int s = ss, e = se;
    int c = t & 15;
    float m = stats[c] * (1.0f / Nn);
    float var = stats[16 + c] * (1.0f / Nn) - m * m;
    float rstd = rsqrtf(var + 1e-5f);
    float sc = rstd * gamma[c];
    float sh = beta[c] - m * sc;

    float sum = 0.f, mx = -3.402823466e+38f;
    for (int r = s + (t >> 4); r < e; r += 16) {
        float v = x3[(size_t)r * 16 + c] * sc + sh;
        v = v > 0.f ? v : 0.1f * v;
        sum += v;
        mx = fmaxf(mx, v);
    }
    ssum[t] = sum; smax[t] = mx;
    __syncthreads();
    for (int off = 128; off >= 16; off >>= 1) {
        if (t < off) { ssum[t] += ssum[t + off]; smax[t] = fmaxf(smax[t], smax[t + off]); }
        __syncthreads();
    }
    if (t < 16) { g_pool[g * 33 + t] = ssum[t]; g_pool[g * 33 + 16 + t] = smax[t]; }
    if (t == 0) g_pool[g * 33 + 32] = (float)(e - s);
}

// ---------------- head (exact round-5) --------------------------------------------
__global__ void k_head(const float* __restrict__ attn_w, const float* __restrict__ attn_b,
                       const float* __restrict__ fc1_w, const float* __restrict__ fc1_b,
                       const float* __restrict__ fc2_w, const float* __restrict__ fc2_b,
                       const float* __restrict__ out_w, const float* __restrict__ out_b,
                       float* __restrict__ out) {
    int g = threadIdx.x;
    if (g >= Gg) return;
    float sm[16], mx[16], mean[16];
    float cnt = g_pool[g * 33 + 32];
    float inv = 1.0f / fmaxf(cnt, 1.0f);
#pragma unroll
    for (int k = 0; k < 16; k++) {
        sm[k] = g_pool[g * 33 + k];
        mx[k] = g_pool[g * 33 + 16 + k];
        mean[k] = sm[k] * inv;
    }
    float z[3];
#pragma unroll
    for (int j = 0; j < 3; j++) z[j] = attn_b[j];
#pragma unroll
    for (int k = 0; k < 16; k++) {
#pragma unroll
        for (int j = 0; j < 3; j++) {
            z[j] += mean[k] * attn_w[k * 3 + j]
                  + mx[k]   * attn_w[(16 + k) * 3 + j]
                  + sm[k]   * attn_w[(32 + k) * 3 + j];
        }
    }
    float zm = fmaxf(z[0], fmaxf(z[1], z[2]));
    float e0 = expf(z[0] - zm), e1 = expf(z[1] - zm), e2 = expf(z[2] - zm);
    float is = 1.f / (e0 + e1 + e2);
    float a0 = e0 * is, a1 = e1 * is, a2 = e2 * is;
    float xg[16];
#pragma unroll
    for (int k = 0; k < 16; k++) xg[k] = a0 * mean[k] + a1 * mx[k] + a2 * sm[k];
    float y1[16];
#pragma unroll
    for (int j = 0; j < 16; j++) {
        float acc = fc1_b[j];
#pragma unroll
        for (int k = 0; k < 16; k++) acc += xg[k] * fc1_w[k * 16 + j];
        y1[j] = acc > 0.f ? acc : 0.1f * acc;
    }
    float y2[8];
#pragma unroll
    for (int j = 0; j < 8; j++) {
        float acc = fc2_b[j];
#pragma unroll
        for (int k = 0; k < 16; k++) acc += y1[k] * fc2_w[k * 8 + j];
        y2[j] = acc > 0.f ? acc : 0.1f * acc;
    }
    float o = out_b[0];
#pragma unroll
    for (int k = 0; k < 8; k++) o += y2[k] * out_w[k];
    out[g] = 1.f / (1.f + expf(-o));
}

// ---------------- host launch (exact round-5 structure) --------------------------
extern "C" void kernel_launch(void* const* d_in, const int* in_sizes, int n_in,
                              void* d_out, int out_size) {
    const float* x      = (const float*)d_in[0];
    const float* W1     = (const float*)d_in[1];
    const float* b1     = (const float*)d_in[2];
    const float* W2     = (const float*)d_in[3];
    const float* b2     = (const float*)d_in[4];
    const float* W3     = (const float*)d_in[5];
    const float* b3     = (const float*)d_in[6];
    const float* g1     = (const float*)d_in[7];
    const float* be1    = (const float*)d_in[8];
    const float* g2     = (const float*)d_in[9];
    const float* be2    = (const float*)d_in[10];
    const float* g3     = (const float*)d_in[11];
    const float* be3    = (const float*)d_in[12];
    const float* attn_w = (const float*)d_in[13];
    const float* attn_b = (const float*)d_in[14];
    const float* fc1_w  = (const float*)d_in[15];
    const float* fc1_b  = (const float*)d_in[16];
    const float* fc2_w  = (const float*)d_in[17];
    const float* fc2_b  = (const float*)d_in[18];
    const float* out_w  = (const float*)d_in[19];
    const float* out_b  = (const float*)d_in[20];
    const int*   ei     = (const int*)d_in[21];
    const int*   batch  = (const int*)d_in[22];

    const int* src = ei;
    const int* dst = ei + Ee;
    float* out = (float*)d_out;

    void *pHA = nullptr, *pHB = nullptr, *pFA = nullptr, *pFB = nullptr, *pS = nullptr;
    cudaGetSymbolAddress(&pHA, g_hA);
    cudaGetSymbolAddress(&pHB, g_hB);
    cudaGetSymbolAddress(&pFA, g_fA);
    cudaGetSymbolAddress(&pFB, g_fB);
    cudaGetSymbolAddress(&pS, g_stats);
    __half* hA = (__half*)pHA;
    __half* hB = (__half*)pHB;
    float* fA = (float*)pFA;
    float* fB = (float*)pFB;
    float* st0 = (float*)pS;
    float* st1 = st0 + 128;
    float* st2 = st0 + 256;

    static cudaStream_t sB = nullptr;
    static cudaEvent_t evFork = nullptr, evJoin = nullptr;
    if (sB == nullptr) {
        cudaStreamCreateWithFlags(&sB, cudaStreamNonBlocking);
        cudaEventCreateWithFlags(&evFork, cudaEventDisableTiming);
        cudaEventCreateWithFlags(&evJoin, cudaEventDisableTiming);
    }

    const int gemm_grid = (Nn + 127) / 128;   // 782
    const int gather_grid = 1184;             // 148 SMs * 8 blocks

    // ---- prefix: degree + dis ----
    k_zero<<<(Nn + 255) / 256, 256>>>();
    k_hist<<<(Ee + 255) / 256, 256>>>(dst);
    k_dis<<<(Nn + 255) / 256, 256>>>();
    cudaEventRecord(evFork, 0);

    // ---- branch B: GEMM1 (needs only dis), fp16 out, overlaps scan/fill ----
    cudaStreamWaitEvent(sB, evFork, 0);
    k_gemm<float, __half, 128, 64, false><<<gemm_grid, 128, 0, sB>>>(
        x, W1, nullptr, nullptr, nullptr, hA);
    cudaEventRecord(evJoin, sB);

    // ---- branch A (main stream): CSR scan + fill ----
    k_scan1<<<SCAN_NB, 512>>>();
    k_scan2<<<1, 256>>>();
    k_scan3<<<SCAN_NB, 512>>>();
    k_fill<<<(Ee + 255) / 256, 256>>>(src, dst);

    // ---- join: layer-1 gather (half2, one load per edge per lane) ----
    cudaStreamWaitEvent(0, evJoin, 0);
    k_gather64h<<<gather_grid, 256>>>((const __half2*)hA, b1, (__half2*)hB, st0);

    // Layer 2: 64 -> 32 (BN1 + lrelu fused into GEMM load; half in, fp32 out)
    k_gemm<__half, float, 64, 32, true><<<gemm_grid, 128>>>(hB, W2, st0, g1, be1, fA);
    k_gather<32><<<gather_grid, 256>>>(fA, b2, fB, st1);

    // Layer 3: 32 -> 16 (BN2 + lrelu fused into GEMM load; fp32 throughout)
    k_gemm<float, float, 32, 16, true><<<gemm_grid, 128>>>(fB, W3, st1, g2, be2, fA);
    k_gather<16><<<gather_grid, 256>>>(fA, b3, fB, st2);

    // Pool (BN3 + lrelu fused) + head
    k_pool<<<Gg, 256>>>(fB, batch, st2, g3, be3);
    k_head<<<1, 64>>>(attn_w, attn_b, fc1_w, fc1_b, fc2_w, fc2_b, out_w, out_b, out);
}

// round 16
// speedup vs baseline: 1.1507x; 1.1507x over previous
#include <cuda_runtime.h>
#include <cuda_bf16.h>
#include <math.h>

#define Nn 100000
#define Ee 1600000
#define Gg 64

// ---------------- packed f32x2 helpers ----------------
#define PACK2(out, a, b) \
    asm("mov.b64 %0, {%1, %2};" : "=l"(out) : "f"(a), "f"(b))
#define FMA2(acc, a, b) \
    asm("fma.rn.f32x2 %0, %1, %2, %0;" : "+l"(acc) : "l"(a), "l"(b))

// ---------------- device scratch (static, no runtime allocation) ----------------
__device__ int   g_cnt[Nn];
__device__ int   g_rowptr[Nn + 1];
__device__ int   g_cursor[Nn];
__device__ int   g_cols[Ee];
__device__ float g_dis[Nn];
__device__ float g_bufA[Nn * 64];
__device__ float g_bufB[Nn * 64];
__device__ float g_stats[3 * 128];      // per layer: [0..H) sum, [H..2H) sumsq
__device__ int   g_bsum[256];           // scan partials
__device__ float g_pool[Gg * 33];       // per graph: sum[16], max[16], count

// ---------------- small utility kernels (exact round-5) -------------------------
__global__ void k_zero() {
    int i = blockIdx.x * 256 + threadIdx.x;
    if (i < Nn) g_cnt[i] = 0;
    if (i < 3 * 128) g_stats[i] = 0.f;
}
__global__ void k_hist(const int* __restrict__ dst) {
    int e = blockIdx.x * 256 + threadIdx.x;
    if (e < Ee) atomicAdd(&g_cnt[dst[e]], 1);
}
__global__ void k_dis() {
    int i = blockIdx.x * 256 + threadIdx.x;
    if (i < Nn) g_dis[i] = rsqrtf((float)(g_cnt[i] + 1));
}

#define SCAN_NB 196   // 196 * 512 = 100352 >= Nn

__global__ void k_scan1() {
    __shared__ int sh[512];
    int t = threadIdx.x, idx = blockIdx.x * 512 + t;
    sh[t] = (idx < Nn) ? g_cnt[idx] : 0;
    __syncthreads();
    for (int off = 256; off > 0; off >>= 1) {
        if (t < off) sh[t] += sh[t + off];
        __syncthreads();
    }
    if (t == 0) g_bsum[blockIdx.x] = sh[0];
}
__global__ void k_scan2() {
    __shared__ int sh[256];
    int t = threadIdx.x;
    int v = (t < SCAN_NB) ? g_bsum[t] : 0;
    sh[t] = v;
    __syncthreads();
    for (int off = 1; off < 256; off <<= 1) {
        int add = (t >= off) ? sh[t - off] : 0;
        __syncthreads();
        sh[t] += add;
        __syncthreads();
    }
    if (t < SCAN_NB) g_bsum[t] = sh[t] - v;   // exclusive
    if (t == 0) g_rowptr[Nn] = Ee;
}
__global__ void k_scan3() {
    __shared__ int sh[512];
    int t = threadIdx.x, idx = blockIdx.x * 512 + t;
    int v = (idx < Nn) ? g_cnt[idx] : 0;
    sh[t] = v;
    __syncthreads();
    for (int off = 1; off < 512; off <<= 1) {
        int add = (t >= off) ? sh[t - off] : 0;
        __syncthreads();
        sh[t] += add;
        __syncthreads();
    }
    if (idx < Nn) {
        int ex = g_bsum[blockIdx.x] + sh[t] - v;
        g_rowptr[idx] = ex;
        g_cursor[idx] = ex;
    }
}
__global__ void k_fill(const int* __restrict__ src, const int* __restrict__ dst) {
    int e = blockIdx.x * 256 + threadIdx.x;
    if (e < Ee) {
        int d = dst[e];
        int p = atomicAdd(&g_cursor[d], 1);
        g_cols[p] = src[e];
    }
}

// ---------------- GEMM1 PIPELINED: W resident, double-buffered xt, reg prefetch --
// out[i,c] = dis[i] * sum_k x[i,k] * W1[k,c] ; K=128, H=64, fp32.
// One sync per chunk (double buffer); next chunk's LDG.128s issued right after
// the sync so they overlap the 16-kk FMA2 phase.
__global__ void __launch_bounds__(128, 4) k_gemm1(const float* __restrict__ x,
                                                  const float* __restrict__ W,
                                                  float* __restrict__ out) {
    __shared__ float Wsm[128 * 64];      // full W1, 32 KB
    __shared__ float xt[2][16][128];     // double-buffered transposed x chunk
    const int tid = threadIdx.x;
    const int base = blockIdx.x * 128;
    const int n0 = (tid & 31) * 4;
    const int cg = tid >> 5;
    const int cbase = cg * 16;           // C = 16 channels per thread

    // preload full W (once)
    {
        const float4* Wg = reinterpret_cast<const float4*>(W);
        float4* Ws = reinterpret_cast<float4*>(Wsm);
#pragma unroll
        for (int i = 0; i < 16; i++) Ws[tid + 128 * i] = Wg[tid + 128 * i];
    }

    unsigned long long acc2[4][8];
#pragma unroll
    for (int t = 0; t < 4; t++)
#pragma unroll
        for (int j = 0; j < 8; j++) acc2[t][j] = 0ull;

    const int myrow = base + tid;
    const bool valid = (myrow < Nn);
    const float* xrow = x + (size_t)myrow * 128;

    // prefetch chunk 0 into registers
    float4 r[4];
#pragma unroll
    for (int q = 0; q < 4; q++) {
        r[q] = make_float4(0.f, 0.f, 0.f, 0.f);
        if (valid) r[q] = *reinterpret_cast<const float4*>(xrow + q * 4);
    }

    for (int kc = 0; kc < 128; kc += 16) {
        const int buf = (kc >> 4) & 1;
        // store prefetched chunk transposed
#pragma unroll
        for (int q = 0; q < 4; q++) {
            xt[buf][q * 4 + 0][tid] = r[q].x;
            xt[buf][q * 4 + 1][tid] = r[q].y;
            xt[buf][q * 4 + 2][tid] = r[q].z;
            xt[buf][q * 4 + 3][tid] = r[q].w;
        }
        __syncthreads();
        // prefetch next chunk (overlaps the compute below)
        if (kc + 16 < 128) {
#pragma unroll
            for (int q = 0; q < 4; q++) {
                r[q] = make_float4(0.f, 0.f, 0.f, 0.f);
                if (valid) r[q] = *reinterpret_cast<const float4*>(xrow + kc + 16 + q * 4);
            }
        }
        // compute chunk
#pragma unroll
        for (int kk = 0; kk < 16; kk++) {
            float4 xv = *reinterpret_cast<const float4*>(&xt[buf][kk][n0]);
            unsigned long long x0, x1, x2, x3;
            PACK2(x0, xv.x, xv.x);
            PACK2(x1, xv.y, xv.y);
            PACK2(x2, xv.z, xv.z);
            PACK2(x3, xv.w, xv.w);
            const ulonglong2* w2 =
                reinterpret_cast<const ulonglong2*>(&Wsm[(kc + kk) * 64 + cbase]);
#pragma unroll
            for (int j = 0; j < 4; j++) {
                ulonglong2 w = w2[j];
                FMA2(acc2[0][2 * j + 0], x0, w.x);
                FMA2(acc2[0][2 * j + 1], x0, w.y);
                FMA2(acc2[1][2 * j + 0], x1, w.x);
                FMA2(acc2[1][2 * j + 1], x1, w.y);
                FMA2(acc2[2][2 * j + 0], x2, w.x);
                FMA2(acc2[2][2 * j + 1], x2, w.y);
                FMA2(acc2[3][2 * j + 0], x3, w.x);
                FMA2(acc2[3][2 * j + 1], x3, w.y);
            }
        }
        // no trailing sync: next iteration writes the OTHER buffer, and the
        // sync there orders its reads against this iteration's compute.
    }

#pragma unroll
    for (int t = 0; t < 4; t++) {
        int node = base + n0 + t;
        if (node < Nn) {
            float dn = g_dis[node];
            const float* a = reinterpret_cast<const float*>(acc2[t]);
            float* o = out + (size_t)node * 64 + cbase;
#pragma unroll
            for (int j = 0; j < 4; j++) {
                float4 rr;
                rr.x = a[4 * j + 0] * dn;
                rr.y = a[4 * j + 1] * dn;
                rr.z = a[4 * j + 2] * dn;
                rr.w = a[4 * j + 3] * dn;
                *reinterpret_cast<float4*>(o + 4 * j) = rr;
            }
        }
    }
}

// ---------------- GEMM (exact round-5 body) for layers 2/3 -----------------------
template <int K, int H, bool NORM>
__global__ void __launch_bounds__(128, 4) k_gemm(const float* __restrict__ h,
                                                 const float* __restrict__ W,
                                                 const float* __restrict__ stats,
                                                 const float* __restrict__ gamma,
                                                 const float* __restrict__ beta,
                                                 float* __restrict__ out) {
    constexpr int C = H / 4;
    __shared__ float Wsm[16 * H];
    __shared__ float xt[16][128];
    __shared__ float nsc[K], nsh[K];
    const int tid = threadIdx.x;
    const int base = blockIdx.x * 128;
    const int n0 = (tid & 31) * 4;
    const int cg = tid >> 5;
    const int cbase = cg * C;

    if (NORM) {
        for (int c = tid; c < K; c += 128) {
            float m = stats[c] * (1.0f / Nn);
            float var = stats[K + c] * (1.0f / Nn) - m * m;
            float rstd = rsqrtf(var + 1e-5f);
            float sc = rstd * gamma[c];
            nsc[c] = sc;
            nsh[c] = beta[c] - m * sc;
        }
        __syncthreads();
    }

    unsigned long long acc2[4][C / 2];
#pragma unroll
    for (int t = 0; t < 4; t++)
#pragma unroll
        for (int j = 0; j < C / 2; j++) acc2[t][j] = 0ull;

    const int myrow = base + tid;

    for (int kc = 0; kc < K; kc += 16) {
        {
            const float4* Wg = reinterpret_cast<const float4*>(W + kc * H);
            float4* Ws = reinterpret_cast<float4*>(Wsm);
#pragma unroll
            for (int i = tid; i < 16 * H / 4; i += 128) Ws[i] = Wg[i];
        }
#pragma unroll
        for (int q = 0; q < 4; q++) {
            float4 v = make_float4(0.f, 0.f, 0.f, 0.f);
            if (myrow < Nn)
                v = *reinterpret_cast<const float4*>(h + (size_t)myrow * K + kc + q * 4);
            if (NORM) {
                int cb = kc + q * 4;
                v.x = v.x * nsc[cb + 0] + nsh[cb + 0]; v.x = v.x > 0.f ? v.x : 0.1f * v.x;
                v.y = v.y * nsc[cb + 1] + nsh[cb + 1]; v.y = v.y > 0.f ? v.y : 0.1f * v.y;
                v.z = v.z * nsc[cb + 2] + nsh[cb + 2]; v.z = v.z > 0.f ? v.z : 0.1f * v.z;
                v.w = v.w * nsc[cb + 3] + nsh[cb + 3]; v.w = v.w > 0.f ? v.w : 0.1f * v.w;
            }
            xt[q * 4 + 0][tid] = v.x;
            xt[q * 4 + 1][tid] = v.y;
            xt[q * 4 + 2][tid] = v.z;
            xt[q * 4 + 3][tid] = v.w;
        }
        __syncthreads();
#pragma unroll
        for (int kk = 0; kk < 16; kk++) {
            float4 xv = *reinterpret_cast<const float4*>(&xt[kk][n0]);
            unsigned long long x0, x1, x2, x3;
            PACK2(x0, xv.x, xv.x);
            PACK2(x1, xv.y, xv.y);
            PACK2(x2, xv.z, xv.z);
            PACK2(x3, xv.w, xv.w);
            const ulonglong2* w2 =
                reinterpret_cast<const ulonglong2*>(&Wsm[kk * H + cbase]);
#pragma unroll
            for (int j = 0; j < C / 4; j++) {
                ulonglong2 w = w2[j];
                FMA2(acc2[0][2 * j + 0], x0, w.x);
                FMA2(acc2[0][2 * j + 1], x0, w.y);
                FMA2(acc2[1][2 * j + 0], x1, w.x);
                FMA2(acc2[1][2 * j + 1], x1, w.y);
                FMA2(acc2[2][2 * j + 0], x2, w.x);
                FMA2(acc2[2][2 * j + 1], x2, w.y);
                FMA2(acc2[3][2 * j + 0], x3, w.x);
                FMA2(acc2[3][2 * j + 1], x3, w.y);
            }
        }
        __syncthreads();
    }

#pragma unroll
    for (int t = 0; t < 4; t++) {
        int node = base + n0 + t;
        if (node < Nn) {
            float dn = g_dis[node];
            const float* a = reinterpret_cast<const float*>(acc2[t]);
            float* o = out + (size_t)node * H + cbase;
#pragma unroll
            for (int j = 0; j < C / 4; j++) {
                float4 r;
                r.x = a[4 * j + 0] * dn;
                r.y = a[4 * j + 1] * dn;
                r.z = a[4 * j + 2] * dn;
                r.w = a[4 * j + 3] * dn;
                *reinterpret_cast<float4*>(o + 4 * j) = r;
            }
        }
    }
}

// ---------------- gather (EXACT round-5 body): one warp per node, scalar NCH ----
template <int H>
__global__ void __launch_bounds__(256) k_gather(const float* __restrict__ hws,
                                                const float* __restrict__ b,
                                                float* __restrict__ pre,
                                                float* __restrict__ stats) {
    constexpr int NCH = (H >= 32) ? H / 32 : 1;
    const int lane = threadIdx.x & 31;
    const int warp = (blockIdx.x * blockDim.x + threadIdx.x) >> 5;
    const int nwarps = (gridDim.x * blockDim.x) >> 5;
    const bool act = (H >= 32) || (lane < H);

    int c[NCH];
#pragma unroll
    for (int j = 0; j < NCH; j++) c[j] = lane + 32 * j;

    float s_sum[NCH], s_sq[NCH];
#pragma unroll
    for (int j = 0; j < NCH; j++) { s_sum[j] = 0.f; s_sq[j] = 0.f; }

    for (int node = warp; node < Nn; node += nwarps) {
        int r0 = g_rowptr[node], r1 = g_rowptr[node + 1];
        float acc[NCH];
        if (act) {
#pragma unroll
            for (int j = 0; j < NCH; j++) acc[j] = hws[(size_t)node * H + c[j]];
        } else {
#pragma unroll
            for (int j = 0; j < NCH; j++) acc[j] = 0.f;
        }
        int p = r0;
        for (; p + 4 <= r1; p += 4) {
            int s0 = g_cols[p], s1 = g_cols[p + 1], s2 = g_cols[p + 2], s3 = g_cols[p + 3];
            if (act) {
#pragma unroll
                for (int j = 0; j < NCH; j++) {
                    float v0 = hws[(size_t)s0 * H + c[j]];
                    float v1 = hws[(size_t)s1 * H + c[j]];
                    float v2 = hws[(size_t)s2 * H + c[j]];
                    float v3 = hws[(size_t)s3 * H + c[j]];
                    acc[j] += (v0 + v1) + (v2 + v3);
                }
            }
        }
        for (; p < r1; p++) {
            int s = g_cols[p];
            if (act) {
#pragma unroll
                for (int j = 0; j < NCH; j++) acc[j] += hws[(size_t)s * H + c[j]];
            }
        }
        if (act) {
            float dn = g_dis[node];
#pragma unroll
            for (int j = 0; j < NCH; j++) {
                float v = dn * acc[j] + b[c[j]];
                pre[(size_t)node * H + c[j]] = v;
                s_sum[j] += v;
                s_sq[j] += v * v;
            }
        }
    }
    if (act) {
#pragma unroll
        for (int j = 0; j < NCH; j++) {
            atomicAdd(&stats[c[j]], s_sum[j]);
            atomicAdd(&stats[H + c[j]], s_sq[j]);
        }
    }
}

// ---------------- pooling (exact round-5) ----------------------------------------
__device__ __forceinline__ int lower_bound_batch(const int* __restrict__ batch, int g) {
    int lo = 0, hi = Nn;
    while (lo < hi) {
        int m = (lo + hi) >> 1;
        if (batch[m] < g) lo = m + 1; else hi = m;
    }
    return lo;
}

__global__ void k_pool(const float* __restrict__ x3, const int* __restrict__ batch,
                       const float* __restrict__ stats,
                       const float* __restrict__ gamma, const float* __restrict__ beta) {
    __shared__ int ss, se;
    __shared__ float ssum[256], smax[256];
    int g = blockIdx.x, t = threadIdx.x;
    if (t == 0) { ss = lower_bound_batch(batch, g); se = lower_bound_batch(batch, g + 1); }
    __syncthreads();
    int s = ss, e = se;
    int c = t & 15;
    float m = stats[c] * (1.0f / Nn);
    float var = stats[16 + c] * (1.0f / Nn) - m * m;
    float rstd = rsqrtf(var + 1e-5f);
    float sc = rstd * gamma[c];
    float sh = beta[c] - m * sc;

    float sum = 0.f, mx = -3.402823466e+38f;
    for (int r = s + (t >> 4); r < e; r += 16) {
        float v = x3[(size_t)r * 16 + c] * sc + sh;
        v = v > 0.f ? v : 0.1f * v;
        sum += v;
        mx = fmaxf(mx, v);
    }
    ssum[t] = sum; smax[t] = mx;
    __syncthreads();
    for (int off = 128; off >= 16; off >>= 1) {
        if (t < off) { ssum[t] += ssum[t + off]; smax[t] = fmaxf(smax[t], smax[t + off]); }
        __syncthreads();
    }
    if (t < 16) { g_pool[g * 33 + t] = ssum[t]; g_pool[g * 33 + 16 + t] = smax[t]; }
    if (t == 0) g_pool[g * 33 + 32] = (float)(e - s);
}

// ---------------- head (exact round-5) --------------------------------------------
__global__ void k_head(const float* __restrict__ attn_w, const float* __restrict__ attn_b,
                       const float* __restrict__ fc1_w, const float* __restrict__ fc1_b,
                       const float* __restrict__ fc2_w, const float* __restrict__ fc2_b,
                       const float* __restrict__ out_w, const float* __restrict__ out_b,
                       float* __restrict__ out) {
    int g = threadIdx.x;
    if (g >= Gg) return;
    float sm[16], mx[16], mean[16];
    float cnt = g_pool[g * 33 + 32];
    float inv = 1.0f / fmaxf(cnt, 1.0f);
#pragma unroll
    for (int k = 0; k < 16; k++) {
        sm[k] = g_pool[g * 33 + k];
        mx[k] = g_pool[g * 33 + 16 + k];
        mean[k] = sm[k] * inv;
    }
    float z[3];
#pragma unroll
    for (int j = 0; j < 3; j++) z[j] = attn_b[j];
#pragma unroll
    for (int k = 0; k < 16; k++) {
#pragma unroll
        for (int j = 0; j < 3; j++) {
            z[j] += mean[k] * attn_w[k * 3 + j]
                  + mx[k]   * attn_w[(16 + k) * 3 + j]
                  + sm[k]   * attn_w[(32 + k) * 3 + j];
        }
    }
    float zm = fmaxf(z[0], fmaxf(z[1], z[2]));
    float e0 = expf(z[0] - zm), e1 = expf(z[1] - zm), e2 = expf(z[2] - zm);
    float is = 1.f / (e0 + e1 + e2);
    float a0 = e0 * is, a1 = e1 * is, a2 = e2 * is;
    float xg[16];
#pragma unroll
    for (int k = 0; k < 16; k++) xg[k] = a0 * mean[k] + a1 * mx[k] + a2 * sm[k];
    float y1[16];
#pragma unroll
    for (int j = 0; j < 16; j++) {
        float acc = fc1_b[j];
#pragma unroll
        for (int k = 0; k < 16; k++) acc += xg[k] * fc1_w[k * 16 + j];
        y1[j] = acc > 0.f ? acc : 0.1f * acc;
    }
    float y2[8];
#pragma unroll
    for (int j = 0; j < 8; j++) {
        float acc = fc2_b[j];
#pragma unroll
        for (int k = 0; k < 16; k++) acc += y1[k] * fc2_w[k * 8 + j];
        y2[j] = acc > 0.f ? acc : 0.1f * acc;
    }
    float o = out_b[0];
#pragma unroll
    for (int k = 0; k < 8; k++) o += y2[k] * out_w[k];
    out[g] = 1.f / (1.f + expf(-o));
}

// ---------------- host launch (exact round-5 structure) --------------------------
extern "C" void kernel_launch(void* const* d_in, const int* in_sizes, int n_in,
                              void* d_out, int out_size) {
    const float* x      = (const float*)d_in[0];
    const float* W1     = (const float*)d_in[1];
    const float* b1     = (const float*)d_in[2];
    const float* W2     = (const float*)d_in[3];
    const float* b2     = (const float*)d_in[4];
    const float* W3     = (const float*)d_in[5];
    const float* b3     = (const float*)d_in[6];
    const float* g1     = (const float*)d_in[7];
    const float* be1    = (const float*)d_in[8];
    const float* g2     = (const float*)d_in[9];
    const float* be2    = (const float*)d_in[10];
    const float* g3     = (const float*)d_in[11];
    const float* be3    = (const float*)d_in[12];
    const float* attn_w = (const float*)d_in[13];
    const float* attn_b = (const float*)d_in[14];
    const float* fc1_w  = (const float*)d_in[15];
    const float* fc1_b  = (const float*)d_in[16];
    const float* fc2_w  = (const float*)d_in[17];
    const float* fc2_b  = (const float*)d_in[18];
    const float* out_w  = (const float*)d_in[19];
    const float* out_b  = (const float*)d_in[20];
    const int*   ei     = (const int*)d_in[21];
    const int*   batch  = (const int*)d_in[22];

    const int* src = ei;
    const int* dst = ei + Ee;
    float* out = (float*)d_out;

    void *pA = nullptr, *pB = nullptr, *pS = nullptr;
    cudaGetSymbolAddress(&pA, g_bufA);
    cudaGetSymbolAddress(&pB, g_bufB);
    cudaGetSymbolAddress(&pS, g_stats);
    float* bufA = (float*)pA;
    float* bufB = (float*)pB;
    float* st0 = (float*)pS;
    float* st1 = st0 + 128;
    float* st2 = st0 + 256;

    static cudaStream_t sB = nullptr;
    static cudaEvent_t evFork = nullptr, evJoin = nullptr;
    if (sB == nullptr) {
        cudaStreamCreateWithFlags(&sB, cudaStreamNonBlocking);
        cudaEventCreateWithFlags(&evFork, cudaEventDisableTiming);
        cudaEventCreateWithFlags(&evJoin, cudaEventDisableTiming);
    }

    const int gemm_grid = (Nn + 127) / 128;   // 782
    const int gather_grid = 1184;             // 148 SMs * 8 blocks

    // ---- prefix: degree + dis ----
    k_zero<<<(Nn + 255) / 256, 256>>>();
    k_hist<<<(Ee + 255) / 256, 256>>>(dst);
    k_dis<<<(Nn + 255) / 256, 256>>>();
    cudaEventRecord(evFork, 0);

    // ---- branch B: pipelined GEMM1 (needs only dis), overlaps scan/fill ----
    cudaStreamWaitEvent(sB, evFork, 0);
    k_gemm1<<<gemm_grid, 128, 0, sB>>>(x, W1, bufA);
    cudaEventRecord(evJoin, sB);

    // ---- branch A (main stream): CSR scan + fill ----
    k_scan1<<<SCAN_NB, 512>>>();
    k_scan2<<<1, 256>>>();
    k_scan3<<<SCAN_NB, 512>>>();
    k_fill<<<(Ee + 255) / 256, 256>>>(src, dst);

    // ---- join: gather needs CSR + GEMM1 output ----
    cudaStreamWaitEvent(0, evJoin, 0);
    k_gather<64><<<gather_grid, 256>>>(bufA, b1, bufB, st0);

    // Layer 2: 64 -> 32 (BN1 + lrelu fused into GEMM load)
    k_gemm<64, 32, true><<<gemm_grid, 128>>>(bufB, W2, st0, g1, be1, bufA);
    k_gather<32><<<gather_grid, 256>>>(bufA, b2, bufB, st1);

    // Layer 3: 32 -> 16 (BN2 + lrelu fused into GEMM load)
    k_gemm<32, 16, true><<<gemm_grid, 128>>>(bufB, W3, st1, g2, be2, bufA);
    k_gather<16><<<gather_grid, 256>>>(bufA, b3, bufB, st2);

    // Pool (BN3 + lrelu fused) + head
    k_pool<<<Gg, 256>>>(bufB, batch, st2, g3, be3);
    k_head<<<1, 64>>>(attn_w, attn_b, fc1_w, fc1_b, fc2_w, fc2_b, out_w, out_b, out);
}